// round 6
// baseline (speedup 1.0000x reference)
#include <cuda_runtime.h>
#include <math.h>

#define Bn 32
#define Cn 512
#define HWn 3136
#define NV4 784             // HWn / 4 (= 3*256 + 16)
#define NROWS (Bn * Cn)     // 16384
#define BPC 8               // batches per chunk
#define RPC (BPC * Cn)      // 4096 rows per chunk

__device__ float g_y[NROWS];

// ---------------------------------------------------------------------------
// Deformable-attention scalar for one (b, p) row. Tiny; L2-hit loads.
// ---------------------------------------------------------------------------
__device__ __forceinline__ float attn_for_row(int row,
                                              const float* __restrict__ w_offset,
                                              const float* __restrict__ w_deform,
                                              const float* __restrict__ b_deform) {
    int b = row >> 9;          // row / Cn
    int p = row & (Cn - 1);
    const float* yb = g_y + b * Cn;
    float acc = b_deform[0];
    #pragma unroll
    for (int k = 0; k < 3; k++) {
        float off = 0.0f;
        #pragma unroll
        for (int j = 0; j < 3; j++) {
            int ii = p + j - 1;
            float yv = (ii >= 0 && ii < Cn) ? yb[ii] : 0.0f;
            off = fmaf(w_offset[k * 3 + j], yv, off);
        }
        float pos = (float)(p + k - 1) + off;
        float p0 = floorf(pos);
        float frac = pos - p0;
        int p0i = (int)p0;
        float v0 = (p0i >= 0     && p0i < Cn)     ? yb[p0i]     : 0.0f;
        float v1 = (p0i + 1 >= 0 && p0i + 1 < Cn) ? yb[p0i + 1] : 0.0f;
        acc = fmaf(w_deform[k], fmaf(v1 - v0, frac, v0), acc);
    }
    return 1.0f / (1.0f + __expf(-acc));
}

// ---------------------------------------------------------------------------
// Pipeline stage: each block fuses ONE mean row (chunk i) and ONE scale row
// (chunk i-1) in a single interleaved per-thread loop, so every warp issues
// paired DRAM-read / L2-read / DRAM-write traffic (the pattern that measured
// ~6.3 TB/s in the plain scale kernel).
//   mean_chunk  < 0 : scale-only (epilogue)
//   scale_chunk < 0 : mean-only  (prologue)
// ---------------------------------------------------------------------------
__global__ void stage_kernel(const float* __restrict__ x,
                             float* __restrict__ out,
                             const float* __restrict__ w_offset,
                             const float* __restrict__ w_deform,
                             const float* __restrict__ b_deform,
                             int mean_chunk, int scale_chunk) {
    const int tid = threadIdx.x;
    const bool do_mean  = (mean_chunk >= 0);
    const bool do_scale = (scale_chunk >= 0);
    const int mean_row  = mean_chunk  * RPC + blockIdx.x;
    const int scale_row = scale_chunk * RPC + blockIdx.x;

    __shared__ float sa;
    __shared__ float part[8];

    float a = 0.0f;
    if (do_scale) {
        if (tid == 0) sa = attn_for_row(scale_row, w_offset, w_deform, b_deform);
        __syncthreads();
        a = sa;
    }

    const float4* xm = (const float4*)(x   + (size_t)mean_row  * HWn);
    const float4* xs = (const float4*)(x   + (size_t)scale_row * HWn);
    float4*       o  = (float4*)      (out + (size_t)scale_row * HWn);

    float s = 0.0f;
    if (do_mean && do_scale) {
        // fused loop: paired read/read-hit/write per iteration
        #pragma unroll
        for (int i = tid; i < NV4; i += 256) {
            float4 vm = __ldg(&xm[i]);       // DRAM read, retain in L2
            float4 vs = __ldcs(&xs[i]);      // L2-hot read, evict-first
            s += (vm.x + vm.y) + (vm.z + vm.w);
            vs.x *= a; vs.y *= a; vs.z *= a; vs.w *= a;
            __stcs(&o[i], vs);               // DRAM write, don't pollute L2
        }
    } else if (do_mean) {
        #pragma unroll
        for (int i = tid; i < NV4; i += 256) {
            float4 vm = __ldg(&xm[i]);
            s += (vm.x + vm.y) + (vm.z + vm.w);
        }
    } else {
        #pragma unroll
        for (int i = tid; i < NV4; i += 256) {
            float4 vs = __ldcs(&xs[i]);
            vs.x *= a; vs.y *= a; vs.z *= a; vs.w *= a;
            __stcs(&o[i], vs);
        }
    }

    if (do_mean) {
        // 256-thread reduction: warp shuffle then cross-warp via smem
        #pragma unroll
        for (int off = 16; off > 0; off >>= 1)
            s += __shfl_down_sync(0xffffffffu, s, off);
        if ((tid & 31) == 0) part[tid >> 5] = s;
        __syncthreads();
        if (tid == 0) {
            float t = part[0] + part[1] + part[2] + part[3]
                    + part[4] + part[5] + part[6] + part[7];
            g_y[mean_row] = t * (1.0f / (float)HWn);
        }
    }
}

extern "C" void kernel_launch(void* const* d_in, const int* in_sizes, int n_in,
                              void* d_out, int out_size) {
    const float* x        = (const float*)d_in[0];
    const float* w_offset = (const float*)d_in[1];
    const float* w_deform = (const float*)d_in[2];
    const float* b_deform = (const float*)d_in[3];
    float* out = (float*)d_out;

    // Pipeline over 4 chunks of 8 batches, one row-pair per block:
    //   K0: mean(c0)
    //   K1: mean(c1)+scale(c0)   (fused per-thread)
    //   K2: mean(c2)+scale(c1)
    //   K3: mean(c3)+scale(c2)
    //   K4: scale(c3)
    stage_kernel<<<RPC, 256>>>(x, out, w_offset, w_deform, b_deform, 0, -1);
    stage_kernel<<<RPC, 256>>>(x, out, w_offset, w_deform, b_deform, 1, 0);
    stage_kernel<<<RPC, 256>>>(x, out, w_offset, w_deform, b_deform, 2, 1);
    stage_kernel<<<RPC, 256>>>(x, out, w_offset, w_deform, b_deform, 3, 2);
    stage_kernel<<<RPC, 256>>>(x, out, w_offset, w_deform, b_deform, -1, 3);
}